// round 6
// baseline (speedup 1.0000x reference)
#include <cuda_runtime.h>

// ForgetMult: h_t = f_t*x_t + (1-f_t)*h_{t-1}
// f,x: (4096, 16, 512) fp32. out inclusive, h_0 = hidden_init.
//
// Hierarchical single-pass scan, float4-vectorized channels:
//   Block = 32 float4-channels (128 fp32) x 16 sub-chunks of 4 steps
//   -> 64 timesteps per block. a,b staged in REGISTERS (8 float4/thread).
//   Block-level Hillis-Steele scan over the 16 sub-chunk composites (16KB
//   smem). Cross-time-block coupling via decoupled look-back by warp 0.
// f,x read exactly once (LDG.128), out written once (STG.128) -> 384MB.

#define SEQ_LEN  4096
#define C4       2048                  // float4 channels (8192 fp32 / 4)
#define SL       4                     // timesteps per thread
#define SUBS     16                    // sub-chunks (warps) per block
#define TILE_C4  32                    // float4 channels per block
#define TB       (SL * SUBS)           // 64 timesteps per block
#define TBLKS    (SEQ_LEN / TB)        // 64
#define TILES    (C4 / TILE_C4)        // 64
#define NTHREADS (TILE_C4 * SUBS)      // 512

__device__ float4 g_aggA[TBLKS * C4];
__device__ float4 g_aggB[TBLKS * C4];
__device__ float4 g_prefH[TBLKS * C4];
__device__ int    g_flag[TBLKS * TILES];  // 0=none 1=agg 2=prefix

__device__ __forceinline__ float4 f4_fma(float4 a, float4 h, float4 b) {
    return make_float4(fmaf(a.x, h.x, b.x), fmaf(a.y, h.y, b.y),
                       fmaf(a.z, h.z, b.z), fmaf(a.w, h.w, b.w));
}
__device__ __forceinline__ float4 f4_mul(float4 a, float4 b) {
    return make_float4(a.x * b.x, a.y * b.y, a.z * b.z, a.w * b.w);
}

__global__ void reset_flags_kernel()
{
    int i = blockIdx.x * blockDim.x + threadIdx.x;
    if (i < TBLKS * TILES) g_flag[i] = 0;
}

__global__ __launch_bounds__(NTHREADS, 2)
void forget_mult_f4_kernel(
    const float4* __restrict__ f,
    const float4* __restrict__ x,
    const float4* __restrict__ h0,
    float4* __restrict__ out)
{
    __shared__ float4 sA[SUBS * TILE_C4];
    __shared__ float4 sB[SUBS * TILE_C4];
    __shared__ float4 sHin[TILE_C4];

    const int tid  = threadIdx.x;
    const int c    = tid & (TILE_C4 - 1);
    const int s    = tid >> 5;
    const int tile = blockIdx.x >> 6;           // / TBLKS
    const int tblk = blockIdx.x & (TBLKS - 1);  // fastest-varying in bid

    const int cg = tile * TILE_C4 + c;
    const int t0 = tblk * TB + s * SL;

    // ---- Phase 1: 8x LDG.128 into registers, fold local composite ----
    const float4* fp = f + (size_t)t0 * C4 + cg;
    const float4* xp = x + (size_t)t0 * C4 + cg;
    float4 ra[SL], rb[SL];
    float4 cA = make_float4(1.f, 1.f, 1.f, 1.f);
    float4 cB = make_float4(0.f, 0.f, 0.f, 0.f);
#pragma unroll
    for (int i = 0; i < SL; i++) {
        float4 ft = __ldcs(fp + (size_t)i * C4);
        float4 xt = __ldcs(xp + (size_t)i * C4);
        float4 a = make_float4(1.f - ft.x, 1.f - ft.y, 1.f - ft.z, 1.f - ft.w);
        float4 b = f4_mul(ft, xt);
        ra[i] = a; rb[i] = b;
        cB = f4_fma(a, cB, b);
        cA = f4_mul(cA, a);
    }

    // ---- Phase 2: Hillis-Steele scan over sub-chunks (per f4 channel) ----
    sA[s * TILE_C4 + c] = cA;
    sB[s * TILE_C4 + c] = cB;
    __syncthreads();
#pragma unroll
    for (int d = 1; d < SUBS; d <<= 1) {
        float4 pA, pB;
        if (s >= d) {
            pA = sA[(s - d) * TILE_C4 + c];
            pB = sB[(s - d) * TILE_C4 + c];
        }
        __syncthreads();
        if (s >= d) {
            cB = f4_fma(cA, pB, cB);   // cur ∘ prev
            cA = f4_mul(cA, pA);
            sA[s * TILE_C4 + c] = cA;
            sB[s * TILE_C4 + c] = cB;
        }
        __syncthreads();
    }
    // Exclusive prefix for phase 4.
    float4 exA = make_float4(1.f, 1.f, 1.f, 1.f);
    float4 exB = make_float4(0.f, 0.f, 0.f, 0.f);
    if (s > 0) {
        exA = sA[(s - 1) * TILE_C4 + c];
        exB = sB[(s - 1) * TILE_C4 + c];
    }

    // ---- Phase 3: cross-time-block look-back (warp 0, lane = f4 channel) ----
    if (tid < TILE_C4) {
        const float4 blkA = sA[(SUBS - 1) * TILE_C4 + tid];
        const float4 blkB = sB[(SUBS - 1) * TILE_C4 + tid];
        const int cg0 = tile * TILE_C4 + tid;
        float4 hin_blk;
        if (tblk == 0) {
            hin_blk = h0[cg0];
        } else {
            g_aggA[(size_t)tblk * C4 + cg0] = blkA;
            g_aggB[(size_t)tblk * C4 + cg0] = blkB;
            __threadfence();
            __syncwarp(0xFFFFFFFFu);
            if (tid == 0)
                *(volatile int*)&g_flag[tblk * TILES + tile] = 1;

            float4 accA = make_float4(1.f, 1.f, 1.f, 1.f);
            float4 accB = make_float4(0.f, 0.f, 0.f, 0.f);
            int j = tblk - 1;
            for (;;) {
                int fl;
                do { fl = *(volatile int*)&g_flag[j * TILES + tile]; } while (fl == 0);
                __threadfence();
                if (fl == 2) {
                    float4 hj = g_prefH[(size_t)j * C4 + cg0];
                    hin_blk = f4_fma(accA, hj, accB);
                    break;
                }
                float4 aj = g_aggA[(size_t)j * C4 + cg0];
                float4 bj = g_aggB[(size_t)j * C4 + cg0];
                accB = f4_fma(accA, bj, accB);
                accA = f4_mul(accA, aj);
                j--;   // tblk 0 always reaches state 2 -> terminates
            }
        }
        g_prefH[(size_t)tblk * C4 + cg0] = f4_fma(blkA, hin_blk, blkB);
        __threadfence();
        __syncwarp(0xFFFFFFFFu);
        if (tid == 0)
            *(volatile int*)&g_flag[tblk * TILES + tile] = 2;
        sHin[tid] = hin_blk;
    }
    __syncthreads();

    // ---- Phase 4: replay from registers, 4x STG.128 ----
    float4 h = f4_fma(exA, sHin[c], exB);
    float4* op = out + (size_t)t0 * C4 + cg;
#pragma unroll
    for (int i = 0; i < SL; i++) {
        h = f4_fma(ra[i], h, rb[i]);
        __stcs(op + (size_t)i * C4, h);
    }
}

extern "C" void kernel_launch(void* const* d_in, const int* in_sizes, int n_in,
                              void* d_out, int out_size)
{
    const float4* f  = (const float4*)d_in[0];
    const float4* x  = (const float4*)d_in[1];
    const float4* h0 = (const float4*)d_in[2];
    float4* out = (float4*)d_out;

    reset_flags_kernel<<<(TBLKS * TILES + 255) / 256, 256>>>();

    dim3 grid(TILES * TBLKS);   // tblk fastest -> predecessors at lower bid
    dim3 block(NTHREADS);
    forget_mult_f4_kernel<<<grid, block>>>(f, x, h0, out);
}

// round 7
// speedup vs baseline: 1.8710x; 1.8710x over previous
#include <cuda_runtime.h>

// ForgetMult: h_t = f_t*x_t + (1-f_t)*h_{t-1}
// f,x: (4096, 16, 512) fp32. out inclusive, h_0 = hidden_init.
//
// Single-pass chunked scan, float4 channels, NO staging:
//   Block = 32 f4-channels (128 fp32) x 16 warps x SL=16 steps -> TB=256
//   timesteps/block, TBLKS=16 (look-back depth <= 15).
//   Phase 1 reads f,x (lines stay L2-resident), folds sub-chunk composites
//   without staging. Phase 4 RE-READS f,x from L2 (slab is L2-hot), rebuilds
//   a,b on the fly, replays, stores. DRAM traffic stays at the 384MB floor;
//   the second read is served by L2.
//   Flag protocol uses ld.acquire.gpu / st.release.gpu (no membar in polls).

#define SEQ_LEN  4096
#define C4       2048                  // float4 channels
#define SL       16                    // timesteps per thread
#define SUBS     16                    // sub-chunks (warps) per block
#define TILE_C4  32                    // f4 channels per block
#define TB       (SL * SUBS)           // 256 timesteps per block
#define TBLKS    (SEQ_LEN / TB)        // 16
#define TILES    (C4 / TILE_C4)        // 64
#define NTHREADS (TILE_C4 * SUBS)      // 512

__device__ float4 g_aggA[TBLKS * C4];
__device__ float4 g_aggB[TBLKS * C4];
__device__ float4 g_prefH[TBLKS * C4];
__device__ int    g_flag[TBLKS * TILES];  // 0=none 1=agg 2=prefix

__device__ __forceinline__ float4 f4_fma(float4 a, float4 h, float4 b) {
    return make_float4(fmaf(a.x, h.x, b.x), fmaf(a.y, h.y, b.y),
                       fmaf(a.z, h.z, b.z), fmaf(a.w, h.w, b.w));
}
__device__ __forceinline__ float4 f4_mul(float4 a, float4 b) {
    return make_float4(a.x * b.x, a.y * b.y, a.z * b.z, a.w * b.w);
}
__device__ __forceinline__ int ld_acquire_gpu(const int* p) {
    int v;
    asm volatile("ld.acquire.gpu.global.b32 %0, [%1];" : "=r"(v) : "l"(p) : "memory");
    return v;
}
__device__ __forceinline__ void st_release_gpu(int* p, int v) {
    asm volatile("st.release.gpu.global.b32 [%0], %1;" :: "l"(p), "r"(v) : "memory");
}

__global__ void reset_flags_kernel()
{
    int i = blockIdx.x * blockDim.x + threadIdx.x;
    if (i < TBLKS * TILES) g_flag[i] = 0;
}

__global__ __launch_bounds__(NTHREADS, 2)
void forget_mult_l2_kernel(
    const float4* __restrict__ f,
    const float4* __restrict__ x,
    const float4* __restrict__ h0,
    float4* __restrict__ out)
{
    __shared__ float4 sA[SUBS * TILE_C4];
    __shared__ float4 sB[SUBS * TILE_C4];
    __shared__ float4 sHin[TILE_C4];

    const int tid  = threadIdx.x;
    const int c    = tid & (TILE_C4 - 1);
    const int s    = tid >> 5;
    const int tile = blockIdx.x >> 4;           // / TBLKS
    const int tblk = blockIdx.x & (TBLKS - 1);  // fastest-varying in bid

    const int cg = tile * TILE_C4 + c;
    const int t0 = tblk * TB + s * SL;

    const float4* fp = f + (size_t)t0 * C4 + cg;
    const float4* xp = x + (size_t)t0 * C4 + cg;

    // ---- Phase 1: stream loads (L2-keep), fold sub-chunk composite.
    // No staging: a,b are rebuilt from L2 in phase 4.
    float4 cA = make_float4(1.f, 1.f, 1.f, 1.f);
    float4 cB = make_float4(0.f, 0.f, 0.f, 0.f);
#pragma unroll
    for (int i = 0; i < SL; i++) {
        float4 ft = fp[(size_t)i * C4];   // default caching -> stays in L2
        float4 xt = xp[(size_t)i * C4];
        float4 a = make_float4(1.f - ft.x, 1.f - ft.y, 1.f - ft.z, 1.f - ft.w);
        float4 b = f4_mul(ft, xt);
        cB = f4_fma(a, cB, b);
        cA = f4_mul(cA, a);
    }

    // ---- Phase 2: Hillis-Steele scan over the 16 sub-chunks ----
    sA[s * TILE_C4 + c] = cA;
    sB[s * TILE_C4 + c] = cB;
    __syncthreads();
#pragma unroll
    for (int d = 1; d < SUBS; d <<= 1) {
        float4 pA, pB;
        if (s >= d) {
            pA = sA[(s - d) * TILE_C4 + c];
            pB = sB[(s - d) * TILE_C4 + c];
        }
        __syncthreads();
        if (s >= d) {
            cB = f4_fma(cA, pB, cB);   // cur ∘ prev
            cA = f4_mul(cA, pA);
            sA[s * TILE_C4 + c] = cA;
            sB[s * TILE_C4 + c] = cB;
        }
        __syncthreads();
    }
    float4 exA = make_float4(1.f, 1.f, 1.f, 1.f);
    float4 exB = make_float4(0.f, 0.f, 0.f, 0.f);
    if (s > 0) {
        exA = sA[(s - 1) * TILE_C4 + c];
        exB = sB[(s - 1) * TILE_C4 + c];
    }

    // ---- Phase 3: cross-time-block look-back (warp 0, depth <= 15) ----
    if (tid < TILE_C4) {
        const float4 blkA = sA[(SUBS - 1) * TILE_C4 + tid];
        const float4 blkB = sB[(SUBS - 1) * TILE_C4 + tid];
        const int cg0 = tile * TILE_C4 + tid;
        float4 hin_blk;
        if (tblk == 0) {
            hin_blk = h0[cg0];
        } else {
            g_aggA[(size_t)tblk * C4 + cg0] = blkA;
            g_aggB[(size_t)tblk * C4 + cg0] = blkB;
            __syncwarp(0xFFFFFFFFu);
            if (tid == 0)
                st_release_gpu(&g_flag[tblk * TILES + tile], 1);

            float4 accA = make_float4(1.f, 1.f, 1.f, 1.f);
            float4 accB = make_float4(0.f, 0.f, 0.f, 0.f);
            int j = tblk - 1;
            for (;;) {
                int fl;
                do { fl = ld_acquire_gpu(&g_flag[j * TILES + tile]); } while (fl == 0);
                if (fl == 2) {
                    float4 hj = g_prefH[(size_t)j * C4 + cg0];
                    hin_blk = f4_fma(accA, hj, accB);
                    break;
                }
                float4 aj = g_aggA[(size_t)j * C4 + cg0];
                float4 bj = g_aggB[(size_t)j * C4 + cg0];
                accB = f4_fma(accA, bj, accB);
                accA = f4_mul(accA, aj);
                j--;   // tblk 0 always reaches state 2 -> terminates
            }
        }
        g_prefH[(size_t)tblk * C4 + cg0] = f4_fma(blkA, hin_blk, blkB);
        __syncwarp(0xFFFFFFFFu);
        if (tid == 0)
            st_release_gpu(&g_flag[tblk * TILES + tile], 2);
        sHin[tid] = hin_blk;
    }
    __syncthreads();

    // ---- Phase 4: re-read f,x (L2-hot), rebuild a,b, replay, store ----
    float4 h = f4_fma(exA, sHin[c], exB);
    float4* op = out + (size_t)t0 * C4 + cg;
#pragma unroll
    for (int i = 0; i < SL; i++) {
        float4 ft = __ldcs(fp + (size_t)i * C4);   // 2nd use: evict-first
        float4 xt = __ldcs(xp + (size_t)i * C4);
        float4 a = make_float4(1.f - ft.x, 1.f - ft.y, 1.f - ft.z, 1.f - ft.w);
        float4 b = f4_mul(ft, xt);
        h = f4_fma(a, h, b);
        __stcs(op + (size_t)i * C4, h);
    }
}

extern "C" void kernel_launch(void* const* d_in, const int* in_sizes, int n_in,
                              void* d_out, int out_size)
{
    const float4* f  = (const float4*)d_in[0];
    const float4* x  = (const float4*)d_in[1];
    const float4* h0 = (const float4*)d_in[2];
    float4* out = (float4*)d_out;

    reset_flags_kernel<<<(TBLKS * TILES + 255) / 256, 256>>>();

    dim3 grid(TILES * TBLKS);   // tblk fastest -> predecessors at lower bid
    dim3 block(NTHREADS);
    forget_mult_l2_kernel<<<grid, block>>>(f, x, h0, out);
}